// round 1
// baseline (speedup 1.0000x reference)
#include <cuda_runtime.h>
#include <math.h>
#include <stdint.h>

// Problem constants
#define B_  2
#define T_  1024
#define C_  768
#define L_  12
#define H_  12
#define V_  50257
#define D_  64
#define BT  (B_*T_)          // 2048
#define C3  (3*C_)           // 2304
#define C4  (4*C_)           // 3072

// ---------------- scratch (device globals; no allocations allowed) ----------
__device__ float g_x  [BT*C_];
__device__ float g_ln [BT*C_];
__device__ float g_qkv[BT*C3];
__device__ float g_att[(size_t)B_*H_*T_*T_];   // ~100 MB
__device__ float g_y  [BT*C_];
__device__ float g_fc [BT*C4];
__device__ float g_logits_fb[(size_t)BT*V_];   // fallback if d_out can't hold logits
__device__ float g_loss_sum;
__device__ int   g_valid_cnt;

// ---------------- helpers ----------------
__device__ __forceinline__ float gelu_f(float x) {
    const float k = 0.7978845608028654f; // sqrt(2/pi)
    float x3 = x * x * x;
    return 0.5f * x * (1.0f + tanhf(k * (x + 0.044715f * x3)));
}

// ---------------- embedding: x = wte[idx] + wpe[t] ----------------
__global__ void embed_k(const int* __restrict__ idx, const float* __restrict__ wte,
                        const float* __restrict__ wpe, float* __restrict__ x) {
    int row = blockIdx.x;            // 0..BT-1
    int t   = row % T_;
    int tok = idx[row];
    const float* pe = wpe + (size_t)t * C_;
    const float* pw = wte + (size_t)tok * C_;
    float* po = x + (size_t)row * C_;
    for (int i = threadIdx.x; i < C_; i += blockDim.x)
        po[i] = pw[i] + pe[i];
}

// ---------------- layernorm over last dim (C=768), one block per row --------
__global__ void layernorm_k(const float* __restrict__ x, const float* __restrict__ w,
                            const float* __restrict__ b, float* __restrict__ out) {
    int row = blockIdx.x;
    const float* px = x + (size_t)row * C_;
    float* po = out + (size_t)row * C_;
    __shared__ float red[256];
    int tid = threadIdx.x;

    float s = 0.f;
    for (int i = tid; i < C_; i += 256) s += px[i];
    red[tid] = s; __syncthreads();
    for (int off = 128; off > 0; off >>= 1) { if (tid < off) red[tid] += red[tid + off]; __syncthreads(); }
    float mean = red[0] * (1.0f / C_);
    __syncthreads();

    float v = 0.f;
    for (int i = tid; i < C_; i += 256) { float d = px[i] - mean; v += d * d; }
    red[tid] = v; __syncthreads();
    for (int off = 128; off > 0; off >>= 1) { if (tid < off) red[tid] += red[tid + off]; __syncthreads(); }
    float rstd = rsqrtf(red[0] * (1.0f / C_) + 1e-5f);

    for (int i = tid; i < C_; i += 256)
        po[i] = (px[i] - mean) * rstd * w[i] + b[i];
}

// ---------------- SGEMM NN: C[M,N] = A[M,K] @ B[K,N] (+bias)(+res / gelu) ---
// Requires: M%128==0, N%128==0, K%16==0 (true for all NN GEMMs here).
#define BM 128
#define BN 128
#define BK 16
#define FUSE_NONE 0
#define FUSE_RES  1
#define FUSE_GELU 2

__global__ __launch_bounds__(256)
void sgemm_nn(const float* __restrict__ A, const float* __restrict__ Bm,
              const float* __restrict__ bias, const float* __restrict__ res,
              float* __restrict__ Cm, int M, int N, int K, int fuse) {
    __shared__ float As[BK][BM];
    __shared__ float Bs[BK][BN];
    int bx = blockIdx.x, by = blockIdx.y;
    int tid = threadIdx.x;
    int trow = (tid / 16) * 8;
    int tcol = (tid % 16) * 8;
    float acc[8][8]; 
    #pragma unroll
    for (int i = 0; i < 8; i++) 
        #pragma unroll
        for (int j = 0; j < 8; j++) acc[i][j] = 0.f;

    const float* Ap = A + (size_t)by * BM * K;
    const float* Bp = Bm + (size_t)bx * BN;

    for (int k0 = 0; k0 < K; k0 += BK) {
        #pragma unroll
        for (int i = 0; i < 2; i++) {
            int idx = tid + i * 256;          // 0..511 float4s for A tile [128x16]
            int r = idx >> 2, c4 = idx & 3;
            float4 v = *(const float4*)(Ap + (size_t)r * K + k0 + c4 * 4);
            As[c4 * 4 + 0][r] = v.x; As[c4 * 4 + 1][r] = v.y;
            As[c4 * 4 + 2][r] = v.z; As[c4 * 4 + 3][r] = v.w;
        }
        #pragma unroll
        for (int i = 0; i < 2; i++) {
            int idx = tid + i * 256;          // 512 float4s for B tile [16x128]
            int r = idx >> 5, c4 = idx & 31;
            *(float4*)&Bs[r][c4 * 4] = *(const float4*)(Bp + (size_t)(k0 + r) * N + c4 * 4);
        }
        __syncthreads();
        #pragma unroll
        for (int kk = 0; kk < BK; kk++) {
            float a[8], b[8];
            #pragma unroll
            for (int i = 0; i < 8; i++) a[i] = As[kk][trow + i];
            #pragma unroll
            for (int j = 0; j < 8; j++) b[j] = Bs[kk][tcol + j];
            #pragma unroll
            for (int i = 0; i < 8; i++)
                #pragma unroll
                for (int j = 0; j < 8; j++) acc[i][j] = fmaf(a[i], b[j], acc[i][j]);
        }
        __syncthreads();
    }

    #pragma unroll
    for (int i = 0; i < 8; i++) {
        int row = by * BM + trow + i;
        #pragma unroll
        for (int j = 0; j < 8; j++) {
            int col = bx * BN + tcol + j;
            float v = acc[i][j];
            if (bias) v += bias[col];
            if (fuse == FUSE_RES)       v += res[(size_t)row * N + col];
            else if (fuse == FUSE_GELU) v = gelu_f(v);
            Cm[(size_t)row * N + col] = v;
        }
    }
}

// ---------------- SGEMM NT: C[M,N] = A[M,K] @ B[N,K]^T  (lm_head) -----------
// M%128==0, K%16==0; N ragged (guarded).
__global__ __launch_bounds__(256)
void sgemm_nt(const float* __restrict__ A, const float* __restrict__ Bm,
              float* __restrict__ Cm, int M, int N, int K) {
    __shared__ float As[BK][BM];
    __shared__ float Bs[BK][BN];
    int bx = blockIdx.x, by = blockIdx.y;
    int tid = threadIdx.x;
    int trow = (tid / 16) * 8;
    int tcol = (tid % 16) * 8;
    float acc[8][8];
    #pragma unroll
    for (int i = 0; i < 8; i++) 
        #pragma unroll
        for (int j = 0; j < 8; j++) acc[i][j] = 0.f;

    const float* Ap = A + (size_t)by * BM * K;

    for (int k0 = 0; k0 < K; k0 += BK) {
        #pragma unroll
        for (int i = 0; i < 2; i++) {
            int idx = tid + i * 256;
            int r = idx >> 2, c4 = idx & 3;
            float4 v = *(const float4*)(Ap + (size_t)r * K + k0 + c4 * 4);
            As[c4 * 4 + 0][r] = v.x; As[c4 * 4 + 1][r] = v.y;
            As[c4 * 4 + 2][r] = v.z; As[c4 * 4 + 3][r] = v.w;
        }
        #pragma unroll
        for (int i = 0; i < 2; i++) {
            int idx = tid + i * 256;
            int r = idx >> 2, c4 = idx & 3;       // r = local n (0..127)
            int n = bx * BN + r;
            float4 v = make_float4(0.f, 0.f, 0.f, 0.f);
            if (n < N) v = *(const float4*)(Bm + (size_t)n * K + k0 + c4 * 4);
            Bs[c4 * 4 + 0][r] = v.x; Bs[c4 * 4 + 1][r] = v.y;
            Bs[c4 * 4 + 2][r] = v.z; Bs[c4 * 4 + 3][r] = v.w;
        }
        __syncthreads();
        #pragma unroll
        for (int kk = 0; kk < BK; kk++) {
            float a[8], b[8];
            #pragma unroll
            for (int i = 0; i < 8; i++) a[i] = As[kk][trow + i];
            #pragma unroll
            for (int j = 0; j < 8; j++) b[j] = Bs[kk][tcol + j];
            #pragma unroll
            for (int i = 0; i < 8; i++)
                #pragma unroll
                for (int j = 0; j < 8; j++) acc[i][j] = fmaf(a[i], b[j], acc[i][j]);
        }
        __syncthreads();
    }

    #pragma unroll
    for (int i = 0; i < 8; i++) {
        int row = by * BM + trow + i;
        #pragma unroll
        for (int j = 0; j < 8; j++) {
            int col = bx * BN + tcol + j;
            if (col < N) Cm[(size_t)row * N + col] = acc[i][j];
        }
    }
}

// ---------------- attention: scores = q @ k^T * 1/sqrt(D), causal -----------
__global__ __launch_bounds__(1024)
void attn_scores(const float* __restrict__ qkv, float* __restrict__ att) {
    int sTile = blockIdx.x, tTile = blockIdx.y, bh = blockIdx.z;
    int b = bh / H_, h = bh % H_;
    int t = tTile * 32 + threadIdx.y;
    int s = sTile * 32 + threadIdx.x;
    size_t out_idx = ((size_t)bh * T_ + t) * T_ + s;

    if (sTile > tTile) { att[out_idx] = -INFINITY; return; }

    __shared__ float qs[32][64];
    __shared__ float ks[32][65];   // pad to avoid 32-way conflicts
    int tid = threadIdx.y * 32 + threadIdx.x;
    for (int i = tid; i < 32 * 64; i += 1024) {
        int r = i >> 6, d = i & 63;
        qs[r][d] = qkv[((size_t)(b * T_ + tTile * 32 + r)) * C3 + h * D_ + d];
        ks[r][d] = qkv[((size_t)(b * T_ + sTile * 32 + r)) * C3 + C_ + h * D_ + d];
    }
    __syncthreads();

    float acc = 0.f;
    #pragma unroll
    for (int d = 0; d < 64; d++) acc = fmaf(qs[threadIdx.y][d], ks[threadIdx.x][d], acc);
    acc *= 0.125f;                       // 1/sqrt(64)
    if (s > t) acc = -INFINITY;
    att[out_idx] = acc;
}

// ---------------- softmax over rows of 1024 ----------------
__global__ void softmax_rows(float* __restrict__ att) {
    size_t row = blockIdx.x;
    float* p = att + row * T_;
    __shared__ float red[256];
    int tid = threadIdx.x;

    float m = -INFINITY;
    for (int i = tid; i < T_; i += 256) m = fmaxf(m, p[i]);
    red[tid] = m; __syncthreads();
    for (int off = 128; off > 0; off >>= 1) { if (tid < off) red[tid] = fmaxf(red[tid], red[tid + off]); __syncthreads(); }
    m = red[0]; __syncthreads();

    float sum = 0.f;
    for (int i = tid; i < T_; i += 256) { float e = expf(p[i] - m); p[i] = e; sum += e; }
    red[tid] = sum; __syncthreads();
    for (int off = 128; off > 0; off >>= 1) { if (tid < off) red[tid] += red[tid + off]; __syncthreads(); }
    float inv = 1.0f / red[0];
    for (int i = tid; i < T_; i += 256) p[i] *= inv;
}

// ---------------- y = att @ v  (per b,h; [32 t] x [64 d] tiles) -------------
__global__ __launch_bounds__(256)
void attn_av(const float* __restrict__ att, const float* __restrict__ qkv,
             float* __restrict__ y) {
    int tTile = blockIdx.x;              // 0..31
    int bh = blockIdx.z;
    int b = bh / H_, h = bh % H_;
    __shared__ float as_[32][33];
    __shared__ float vs[32][64];
    int tid = threadIdx.x;
    int trow = (tid / 16) * 2;           // 0..30
    int tcol = (tid % 16) * 4;           // 0..60
    float acc[2][4] = {{0.f,0.f,0.f,0.f},{0.f,0.f,0.f,0.f}};

    int nS = tTile + 1;                  // causal: s tiles 0..tTile
    for (int st = 0; st < nS; st++) {
        for (int i = tid; i < 32 * 32; i += 256) {
            int r = i >> 5, c = i & 31;
            as_[r][c] = att[((size_t)bh * T_ + tTile * 32 + r) * T_ + st * 32 + c];
        }
        for (int i = tid; i < 32 * 64; i += 256) {
            int r = i >> 6, d = i & 63;
            vs[r][d] = qkv[((size_t)(b * T_ + st * 32 + r)) * C3 + 2 * C_ + h * D_ + d];
        }
        __syncthreads();
        #pragma unroll
        for (int kk = 0; kk < 32; kk++) {
            float a0 = as_[trow][kk], a1 = as_[trow + 1][kk];
            #pragma unroll
            for (int j = 0; j < 4; j++) {
                float v = vs[kk][tcol + j];
                acc[0][j] = fmaf(a0, v, acc[0][j]);
                acc[1][j] = fmaf(a1, v, acc[1][j]);
            }
        }
        __syncthreads();
    }
    #pragma unroll
    for (int i = 0; i < 2; i++)
        #pragma unroll
        for (int j = 0; j < 4; j++)
            y[((size_t)(b * T_ + tTile * 32 + trow + i)) * C_ + h * D_ + tcol + j] = acc[i][j];
}

// ---------------- loss ----------------
__global__ void zero_loss_k() { g_loss_sum = 0.f; g_valid_cnt = 0; }

__global__ void loss_rows(const float* __restrict__ logits, const int* __restrict__ targets) {
    int row = blockIdx.x;
    const float* p = logits + (size_t)row * V_;
    __shared__ float red[256];
    int tid = threadIdx.x;

    float m = -INFINITY;
    for (int i = tid; i < V_; i += 256) m = fmaxf(m, p[i]);
    red[tid] = m; __syncthreads();
    for (int off = 128; off > 0; off >>= 1) { if (tid < off) red[tid] = fmaxf(red[tid], red[tid + off]); __syncthreads(); }
    m = red[0]; __syncthreads();

    float sum = 0.f;
    for (int i = tid; i < V_; i += 256) sum += expf(p[i] - m);
    red[tid] = sum; __syncthreads();
    for (int off = 128; off > 0; off >>= 1) { if (tid < off) red[tid] += red[tid + off]; __syncthreads(); }
    sum = red[0];

    if (tid == 0) {
        int t = targets[row];
        if (t != -1) {
            float nll = -(p[t] - m - logf(sum));
            atomicAdd(&g_loss_sum, nll);
            atomicAdd(&g_valid_cnt, 1);
        }
    }
}

__global__ void finalize_loss(float* out, int loss_idx) {
    int v = g_valid_cnt; if (v < 1) v = 1;
    out[loss_idx] = g_loss_sum / (float)v;
}

// ---------------- host launcher ----------------
extern "C" void kernel_launch(void* const* d_in, const int* in_sizes, int n_in,
                              void* d_out, int out_size) {
    const int*   idx     = (const int*)  d_in[0];
    const int*   targets = (const int*)  d_in[1];
    const float* wte     = (const float*)d_in[2];
    const float* wpe     = (const float*)d_in[3];
    const float* ln1_w   = (const float*)d_in[4];
    const float* ln1_b   = (const float*)d_in[5];
    const float* attn_w  = (const float*)d_in[6];
    const float* attn_b  = (const float*)d_in[7];
    const float* aproj_w = (const float*)d_in[8];
    const float* aproj_b = (const float*)d_in[9];
    const float* ln2_w   = (const float*)d_in[10];
    const float* ln2_b   = (const float*)d_in[11];
    const float* fc_w    = (const float*)d_in[12];
    const float* fc_b    = (const float*)d_in[13];
    const float* mproj_w = (const float*)d_in[14];
    const float* mproj_b = (const float*)d_in[15];
    const float* lnf_w   = (const float*)d_in[16];
    const float* lnf_b   = (const float*)d_in[17];

    float *px, *pln, *pqkv, *patt, *py, *pfc, *pfb;
    cudaGetSymbolAddress((void**)&px,   g_x);
    cudaGetSymbolAddress((void**)&pln,  g_ln);
    cudaGetSymbolAddress((void**)&pqkv, g_qkv);
    cudaGetSymbolAddress((void**)&patt, g_att);
    cudaGetSymbolAddress((void**)&py,   g_y);
    cudaGetSymbolAddress((void**)&pfc,  g_fc);
    cudaGetSymbolAddress((void**)&pfb,  g_logits_fb);

    const long long BTV = (long long)BT * V_;
    float* logits = ((long long)out_size >= BTV) ? (float*)d_out : pfb;

    embed_k<<<BT, 256>>>(idx, wte, wpe, px);

    for (int l = 0; l < L_; l++) {
        layernorm_k<<<BT, 256>>>(px, ln1_w + (size_t)l * C_, ln1_b + (size_t)l * C_, pln);
        sgemm_nn<<<dim3(C3 / BN, BT / BM), 256>>>(pln, attn_w + (size_t)l * C_ * C3,
                                                  attn_b + (size_t)l * C3, nullptr, pqkv,
                                                  BT, C3, C_, FUSE_NONE);
        attn_scores<<<dim3(T_ / 32, T_ / 32, B_ * H_), dim3(32, 32)>>>(pqkv, patt);
        softmax_rows<<<B_ * H_ * T_, 256>>>(patt);
        attn_av<<<dim3(T_ / 32, 1, B_ * H_), 256>>>(patt, pqkv, py);
        sgemm_nn<<<dim3(C_ / BN, BT / BM), 256>>>(py, aproj_w + (size_t)l * C_ * C_,
                                                  aproj_b + (size_t)l * C_, px, px,
                                                  BT, C_, C_, FUSE_RES);
        layernorm_k<<<BT, 256>>>(px, ln2_w + (size_t)l * C_, ln2_b + (size_t)l * C_, pln);
        sgemm_nn<<<dim3(C4 / BN, BT / BM), 256>>>(pln, fc_w + (size_t)l * C_ * C4,
                                                  fc_b + (size_t)l * C4, nullptr, pfc,
                                                  BT, C4, C_, FUSE_GELU);
        sgemm_nn<<<dim3(C_ / BN, BT / BM), 256>>>(pfc, mproj_w + (size_t)l * C4 * C_,
                                                  mproj_b + (size_t)l * C_, px, px,
                                                  BT, C_, C4, FUSE_RES);
    }

    layernorm_k<<<BT, 256>>>(px, lnf_w, lnf_b, pln);

    int nbx = (V_ + BN - 1) / BN;   // 393
    sgemm_nt<<<dim3(nbx, BT / BM), 256>>>(pln, wte, logits, BT, V_, C_);

    zero_loss_k<<<1, 1>>>();
    loss_rows<<<BT, 256>>>(logits, targets);

    int loss_idx = -1;
    if ((long long)out_size == BTV + 1) loss_idx = (int)BTV;
    else if (out_size == 1)             loss_idx = 0;
    if (loss_idx >= 0) finalize_loss<<<1, 1>>>((float*)d_out, loss_idx);
}

// round 4
// speedup vs baseline: 1.9019x; 1.9019x over previous
#include <cuda_runtime.h>
#include <cuda_bf16.h>
#include <math.h>
#include <stdint.h>

#define B_  2
#define T_  1024
#define C_  768
#define L_  12
#define H_  12
#define V_  50257
#define D_  64
#define BT  (B_*T_)          // 2048
#define C3  (3*C_)           // 2304
#define C4  (4*C_)           // 3072

typedef __nv_bfloat16 bf16;

// ---------------- scratch (device globals) ----------------
__device__ float g_x  [BT*C_];
__device__ float g_ln [BT*C_];
__device__ float g_qkv[BT*C3];
__device__ float g_att[(size_t)B_*H_*T_*T_];
__device__ float g_y  [BT*C_];
__device__ float g_fc [BT*C4];
__device__ float g_logits_fb[(size_t)BT*V_];
__device__ float g_loss_sum;
__device__ int   g_valid_cnt;

// split-bf16 buffers
__device__ bf16 g_ah[BT*C4], g_al[BT*C4];
__device__ bf16 g_wqkv_h[(size_t)L_*C_*C3], g_wqkv_l[(size_t)L_*C_*C3];
__device__ bf16 g_wapr_h[(size_t)L_*C_*C_], g_wapr_l[(size_t)L_*C_*C_];
__device__ bf16 g_wfc_h [(size_t)L_*C_*C4], g_wfc_l [(size_t)L_*C_*C4];
__device__ bf16 g_wmp_h [(size_t)L_*C4*C_], g_wmp_l [(size_t)L_*C4*C_];
__device__ bf16 g_wte_h [(size_t)V_*C_],    g_wte_l [(size_t)V_*C_];

// ---------------- ptx helpers ----------------
__device__ __forceinline__ uint32_t smem_u32(const void* p) {
    uint32_t a;
    asm("{ .reg .u64 t; cvta.to.shared.u64 t, %1; cvt.u32.u64 %0, t; }" : "=r"(a) : "l"(p));
    return a;
}
template<int N> __device__ __forceinline__ void cp_wait() {
    asm volatile("cp.async.wait_group %0;" :: "n"(N) : "memory");
}
__device__ __forceinline__ void cp_commit() {
    asm volatile("cp.async.commit_group;" ::: "memory");
}
__device__ __forceinline__ void cp16(uint32_t dst, const void* src, int sz) {
    asm volatile("cp.async.cg.shared.global [%0], [%1], 16, %2;"
                 :: "r"(dst), "l"(src), "r"(sz) : "memory");
}
__device__ __forceinline__ void ldsm4(uint32_t* r, uint32_t a) {
    asm volatile("ldmatrix.sync.aligned.m8n8.x4.shared.b16 {%0,%1,%2,%3}, [%4];"
                 : "=r"(r[0]), "=r"(r[1]), "=r"(r[2]), "=r"(r[3]) : "r"(a));
}
__device__ __forceinline__ void mma16816(float* d, const uint32_t* a, const uint32_t* b) {
    asm volatile("mma.sync.aligned.m16n8k16.row.col.f32.bf16.bf16.f32 "
                 "{%0,%1,%2,%3}, {%4,%5,%6,%7}, {%8,%9}, {%0,%1,%2,%3};"
                 : "+f"(d[0]), "+f"(d[1]), "+f"(d[2]), "+f"(d[3])
                 : "r"(a[0]), "r"(a[1]), "r"(a[2]), "r"(a[3]), "r"(b[0]), "r"(b[1]));
}

__device__ __forceinline__ float gelu_f(float x) {
    const float k = 0.7978845608028654f;
    float x3 = x * x * x;
    return 0.5f * x * (1.0f + tanhf(k * (x + 0.044715f * x3)));
}

// ---------------- split-bf16 conversion kernels ----------------
__global__ void convert_split(const float* __restrict__ in, bf16* __restrict__ hi,
                              bf16* __restrict__ lo, int n) {
    int i = blockIdx.x * blockDim.x + threadIdx.x;
    int stride = gridDim.x * blockDim.x;
    for (; i < n; i += stride) {
        float v = in[i];
        bf16 h = __float2bfloat16_rn(v);
        hi[i] = h;
        lo[i] = __float2bfloat16_rn(v - __bfloat162float(h));
    }
}

// in: [K,N] row-major per layer -> out: [N,K] hi/lo per layer
__global__ void transpose_split(const float* __restrict__ in, bf16* __restrict__ hi,
                                bf16* __restrict__ lo, int K, int N) {
    int l = blockIdx.z;
    in += (size_t)l * K * N;
    hi += (size_t)l * K * N;
    lo += (size_t)l * K * N;
    __shared__ float t[32][33];
    int n0 = blockIdx.x * 32, k0 = blockIdx.y * 32;
    #pragma unroll
    for (int i = 0; i < 4; i++) {
        int k = threadIdx.y + i * 8;
        t[k][threadIdx.x] = in[(size_t)(k0 + k) * N + n0 + threadIdx.x];
    }
    __syncthreads();
    #pragma unroll
    for (int i = 0; i < 4; i++) {
        int n = threadIdx.y + i * 8;
        float v = t[threadIdx.x][n];
        bf16 h = __float2bfloat16_rn(v);
        size_t o = (size_t)(n0 + n) * K + k0 + threadIdx.x;
        hi[o] = h;
        lo[o] = __float2bfloat16_rn(v - __bfloat162float(h));
    }
}

// ---------------- HMMA split-bf16 GEMM ----------------
// C[M,N] = Ah@Bh^T + Ah@Bl^T + Al@Bh^T   A:[M,K] K-major, B:[N,K] K-major
// CTA 128x128, BK=32, 8 warps (4m x 2n -> 32x64 warp tile), cp.async 2-stage.
#define FUSE_NONE 0
#define FUSE_RES  1
#define FUSE_GELU 2
// stage layout: AH 0, AL 8192, BH 16384, BL 24576; stage stride 32768
#define GSTG 32768
#define GSM_TOTAL (2*GSTG)

// swizzled byte offset within a 128x32 bf16 tile (64B rows, 16B col-blocks)
__device__ __forceinline__ uint32_t swoff(int r, int c) {
    return (uint32_t)(r * 64 + ((c ^ ((r >> 1) & 3)) << 4));
}

__global__ __launch_bounds__(256)
void gemm_hmma(const bf16* __restrict__ Ah, const bf16* __restrict__ Al,
               const bf16* __restrict__ Bh, const bf16* __restrict__ Bl,
               const float* __restrict__ bias, const float* __restrict__ res,
               float* __restrict__ Cm, int M, int N, int K, int fuse) {
    extern __shared__ char smem[];
    uint32_t sb = smem_u32(smem);
    int tid = threadIdx.x, lane = tid & 31, w = tid >> 5;
    int wm0 = (w & 3) * 32, wn0 = (w >> 2) * 64;
    int m0 = blockIdx.y * 128, n0 = blockIdx.x * 128;

    float acc[2][8][4];
    #pragma unroll
    for (int i = 0; i < 2; i++)
        #pragma unroll
        for (int j = 0; j < 8; j++)
            #pragma unroll
            for (int k = 0; k < 4; k++) acc[i][j][k] = 0.f;

    int cr = tid >> 2, cb = tid & 3;
    int nch = K >> 5;
    int rowoff = (lane & 7) + ((lane >> 3) & 1) * 8;  // ldmatrix row-within-16
    int cbh = lane >> 4;                              // ldmatrix k-halfblock

    // prologue: chunk 0 -> stage 0
    {
        uint32_t base = sb;
        #pragma unroll
        for (int i = 0; i < 2; i++) {
            int r = cr + i * 64;
            uint32_t d = swoff(r, cb);
            size_t ao = (size_t)(m0 + r) * K + cb * 8;
            cp16(base + d, Ah + ao, 16);
            cp16(base + 8192 + d, Al + ao, 16);
            int nr = n0 + r;
            int nc = nr < N ? nr : (N - 1);
            int sz = nr < N ? 16 : 0;
            size_t bo = (size_t)nc * K + cb * 8;
            cp16(base + 16384 + d, Bh + bo, sz);
            cp16(base + 24576 + d, Bl + bo, sz);
        }
        cp_commit();
    }

    for (int ch = 0; ch < nch; ch++) {
        if (ch + 1 < nch) {
            int k0 = (ch + 1) * 32;
            uint32_t base = sb + ((ch + 1) & 1) * GSTG;
            #pragma unroll
            for (int i = 0; i < 2; i++) {
                int r = cr + i * 64;
                uint32_t d = swoff(r, cb);
                size_t ao = (size_t)(m0 + r) * K + k0 + cb * 8;
                cp16(base + d, Ah + ao, 16);
                cp16(base + 8192 + d, Al + ao, 16);
                int nr = n0 + r;
                int nc = nr < N ? nr : (N - 1);
                int sz = nr < N ? 16 : 0;
                size_t bo = (size_t)nc * K + k0 + cb * 8;
                cp16(base + 16384 + d, Bh + bo, sz);
                cp16(base + 24576 + d, Bl + bo, sz);
            }
            cp_commit();
            cp_wait<1>();
        } else {
            cp_wait<0>();
        }
        __syncthreads();

        uint32_t aB = sb + (ch & 1) * GSTG;
        uint32_t bB = aB + 16384;
        #pragma unroll
        for (int ks = 0; ks < 2; ks++) {
            uint32_t ah[2][4], al[2][4];
            #pragma unroll
            for (int mi = 0; mi < 2; mi++) {
                int row = wm0 + mi * 16 + rowoff;
                uint32_t ad = aB + (uint32_t)(row * 64) +
                              (uint32_t)((((2 * ks + cbh) ^ ((row >> 1) & 3))) << 4);
                ldsm4(ah[mi], ad);
                ldsm4(al[mi], ad + 8192);
            }
            uint32_t bh[8][2], bl[8][2];
            #pragma unroll
            for (int nj = 0; nj < 4; nj++) {
                int row = wn0 + nj * 16 + rowoff;
                uint32_t bd = bB + (uint32_t)(row * 64) +
                              (uint32_t)((((2 * ks + cbh) ^ ((row >> 1) & 3))) << 4);
                uint32_t q[4];
                ldsm4(q, bd);
                bh[2 * nj][0] = q[0]; bh[2 * nj][1] = q[2];
                bh[2 * nj + 1][0] = q[1]; bh[2 * nj + 1][1] = q[3];
                ldsm4(q, bd + 8192);
                bl[2 * nj][0] = q[0]; bl[2 * nj][1] = q[2];
                bl[2 * nj + 1][0] = q[1]; bl[2 * nj + 1][1] = q[3];
            }
            #pragma unroll
            for (int mi = 0; mi < 2; mi++)
                #pragma unroll
                for (int ni = 0; ni < 8; ni++) {
                    mma16816(acc[mi][ni], ah[mi], bh[ni]);
                    mma16816(acc[mi][ni], ah[mi], bl[ni]);
                    mma16816(acc[mi][ni], al[mi], bh[ni]);
                }
        }
        __syncthreads();
    }

    // epilogue (float2 stores only when N is even: N odd => row parity breaks 8B alignment)
    int r0 = lane >> 2, c0 = (lane & 3) * 2;
    bool vec_ok = (n0 + 128 <= N) && ((N & 1) == 0);
    #pragma unroll
    for (int mi = 0; mi < 2; mi++) {
        #pragma unroll
        for (int ni = 0; ni < 8; ni++) {
            int gr = m0 + wm0 + mi * 16 + r0;
            int gc = n0 + wn0 + ni * 8 + c0;
            float v0 = acc[mi][ni][0], v1 = acc[mi][ni][1];
            float v2 = acc[mi][ni][2], v3 = acc[mi][ni][3];
            if (vec_ok) {
                if (bias) { float b0 = bias[gc], b1 = bias[gc + 1]; v0 += b0; v1 += b1; v2 += b0; v3 += b1; }
                if (fuse == FUSE_RES) {
                    const float* r1p = res + (size_t)gr * N + gc;
                    const float* r2p = res + (size_t)(gr + 8) * N + gc;
                    v0 += r1p[0]; v1 += r1p[1]; v2 += r2p[0]; v3 += r2p[1];
                } else if (fuse == FUSE_GELU) {
                    v0 = gelu_f(v0); v1 = gelu_f(v1); v2 = gelu_f(v2); v3 = gelu_f(v3);
                }
                *(float2*)(Cm + (size_t)gr * N + gc)       = make_float2(v0, v1);
                *(float2*)(Cm + (size_t)(gr + 8) * N + gc) = make_float2(v2, v3);
            } else {
                if (gc < N) {
                    float b0 = bias ? bias[gc] : 0.f;
                    float a0 = v0 + b0, a2 = v2 + b0;
                    if (fuse == FUSE_RES) { a0 += res[(size_t)gr * N + gc]; a2 += res[(size_t)(gr + 8) * N + gc]; }
                    else if (fuse == FUSE_GELU) { a0 = gelu_f(a0); a2 = gelu_f(a2); }
                    Cm[(size_t)gr * N + gc] = a0;
                    Cm[(size_t)(gr + 8) * N + gc] = a2;
                }
                if (gc + 1 < N) {
                    float b1 = bias ? bias[gc + 1] : 0.f;
                    float a1 = v1 + b1, a3 = v3 + b1;
                    if (fuse == FUSE_RES) { a1 += res[(size_t)gr * N + gc + 1]; a3 += res[(size_t)(gr + 8) * N + gc + 1]; }
                    else if (fuse == FUSE_GELU) { a1 = gelu_f(a1); a3 = gelu_f(a3); }
                    Cm[(size_t)gr * N + gc + 1] = a1;
                    Cm[(size_t)(gr + 8) * N + gc + 1] = a3;
                }
            }
        }
    }
}

// ---------------- embedding ----------------
__global__ void embed_k(const int* __restrict__ idx, const float* __restrict__ wte,
                        const float* __restrict__ wpe, float* __restrict__ x) {
    int row = blockIdx.x;
    int t = row % T_;
    int tok = idx[row];
    const float* pe = wpe + (size_t)t * C_;
    const float* pw = wte + (size_t)tok * C_;
    float* po = x + (size_t)row * C_;
    for (int i = threadIdx.x; i < C_; i += blockDim.x) po[i] = pw[i] + pe[i];
}

// ---------------- layernorm ----------------
__global__ void layernorm_k(const float* __restrict__ x, const float* __restrict__ w,
                            const float* __restrict__ b, float* __restrict__ out) {
    int row = blockIdx.x;
    const float* px = x + (size_t)row * C_;
    float* po = out + (size_t)row * C_;
    __shared__ float red[256];
    int tid = threadIdx.x;

    float s = 0.f;
    for (int i = tid; i < C_; i += 256) s += px[i];
    red[tid] = s; __syncthreads();
    for (int off = 128; off > 0; off >>= 1) { if (tid < off) red[tid] += red[tid + off]; __syncthreads(); }
    float mean = red[0] * (1.0f / C_);
    __syncthreads();

    float v = 0.f;
    for (int i = tid; i < C_; i += 256) { float d = px[i] - mean; v += d * d; }
    red[tid] = v; __syncthreads();
    for (int off = 128; off > 0; off >>= 1) { if (tid < off) red[tid] += red[tid + off]; __syncthreads(); }
    float rstd = rsqrtf(red[0] * (1.0f / C_) + 1e-5f);

    for (int i = tid; i < C_; i += 256)
        po[i] = (px[i] - mean) * rstd * w[i] + b[i];
}

// ---------------- attention ----------------
__global__ __launch_bounds__(1024)
void attn_scores(const float* __restrict__ qkv, float* __restrict__ att) {
    int sTile = blockIdx.x, tTile = blockIdx.y, bh = blockIdx.z;
    if (sTile > tTile) return;
    int b = bh / H_, h = bh % H_;
    int t = tTile * 32 + threadIdx.y;
    int s = sTile * 32 + threadIdx.x;

    __shared__ float qs[32][64];
    __shared__ float ks[32][65];
    int tid = threadIdx.y * 32 + threadIdx.x;
    for (int i = tid; i < 32 * 64; i += 1024) {
        int r = i >> 6, d = i & 63;
        qs[r][d] = qkv[((size_t)(b * T_ + tTile * 32 + r)) * C3 + h * D_ + d];
        ks[r][d] = qkv[((size_t)(b * T_ + sTile * 32 + r)) * C3 + C_ + h * D_ + d];
    }
    __syncthreads();

    float acc = 0.f;
    #pragma unroll
    for (int d = 0; d < 64; d++) acc = fmaf(qs[threadIdx.y][d], ks[threadIdx.x][d], acc);
    acc *= 0.125f;
    att[((size_t)bh * T_ + t) * T_ + s] = (s > t) ? 0.0f : acc;
}

__global__ void softmax_rows(float* __restrict__ att) {
    size_t row = blockIdx.x;
    int len = (int)(row % T_) + 1;
    float* p = att + row * T_;
    __shared__ float red[256];
    int tid = threadIdx.x;

    float m = -INFINITY;
    for (int i = tid; i < len; i += 256) m = fmaxf(m, p[i]);
    red[tid] = m; __syncthreads();
    for (int off = 128; off > 0; off >>= 1) { if (tid < off) red[tid] = fmaxf(red[tid], red[tid + off]); __syncthreads(); }
    m = red[0]; __syncthreads();

    float sum = 0.f;
    for (int i = tid; i < len; i += 256) { float e = expf(p[i] - m); p[i] = e; sum += e; }
    red[tid] = sum; __syncthreads();
    for (int off = 128; off > 0; off >>= 1) { if (tid < off) red[tid] += red[tid + off]; __syncthreads(); }
    float inv = 1.0f / red[0];
    for (int i = tid; i < len; i += 256) p[i] *= inv;
}

__global__ __launch_bounds__(256)
void attn_av(const float* __restrict__ att, const float* __restrict__ qkv,
             float* __restrict__ y) {
    int tTile = blockIdx.x;
    int bh = blockIdx.z;
    int b = bh / H_, h = bh % H_;
    __shared__ float as_[32][33];
    __shared__ float vs[32][64];
    int tid = threadIdx.x;
    int trow = (tid / 16) * 2;
    int tcol = (tid % 16) * 4;
    float acc[2][4] = {{0.f,0.f,0.f,0.f},{0.f,0.f,0.f,0.f}};

    int nS = tTile + 1;
    for (int st = 0; st < nS; st++) {
        for (int i = tid; i < 32 * 32; i += 256) {
            int r = i >> 5, c = i & 31;
            as_[r][c] = att[((size_t)bh * T_ + tTile * 32 + r) * T_ + st * 32 + c];
        }
        for (int i = tid; i < 32 * 64; i += 256) {
            int r = i >> 6, d = i & 63;
            vs[r][d] = qkv[((size_t)(b * T_ + st * 32 + r)) * C3 + 2 * C_ + h * D_ + d];
        }
        __syncthreads();
        #pragma unroll
        for (int kk = 0; kk < 32; kk++) {
            float a0 = as_[trow][kk], a1 = as_[trow + 1][kk];
            #pragma unroll
            for (int j = 0; j < 4; j++) {
                float v = vs[kk][tcol + j];
                acc[0][j] = fmaf(a0, v, acc[0][j]);
                acc[1][j] = fmaf(a1, v, acc[1][j]);
            }
        }
        __syncthreads();
    }
    #pragma unroll
    for (int i = 0; i < 2; i++)
        #pragma unroll
        for (int j = 0; j < 4; j++)
            y[((size_t)(b * T_ + tTile * 32 + trow + i)) * C_ + h * D_ + tcol + j] = acc[i][j];
}

// ---------------- loss ----------------
__global__ void zero_loss_k() { g_loss_sum = 0.f; g_valid_cnt = 0; }

__global__ void loss_rows(const float* __restrict__ logits, const int* __restrict__ targets) {
    int row = blockIdx.x;
    const float* p = logits + (size_t)row * V_;
    __shared__ float red[256];
    int tid = threadIdx.x;

    float m = -INFINITY;
    for (int i = tid; i < V_; i += 256) m = fmaxf(m, p[i]);
    red[tid] = m; __syncthreads();
    for (int off = 128; off > 0; off >>= 1) { if (tid < off) red[tid] = fmaxf(red[tid], red[tid + off]); __syncthreads(); }
    m = red[0]; __syncthreads();

    float sum = 0.f;
    for (int i = tid; i < V_; i += 256) sum += expf(p[i] - m);
    red[tid] = sum; __syncthreads();
    for (int off = 128; off > 0; off >>= 1) { if (tid < off) red[tid] += red[tid + off]; __syncthreads(); }
    sum = red[0];

    if (tid == 0) {
        int t = targets[row];
        if (t != -1) {
            float nll = -(p[t] - m - logf(sum));
            atomicAdd(&g_loss_sum, nll);
            atomicAdd(&g_valid_cnt, 1);
        }
    }
}

__global__ void finalize_loss(float* out, int loss_idx) {
    int v = g_valid_cnt; if (v < 1) v = 1;
    out[loss_idx] = g_loss_sum / (float)v;
}

// ---------------- host launcher ----------------
extern "C" void kernel_launch(void* const* d_in, const int* in_sizes, int n_in,
                              void* d_out, int out_size) {
    const int*   idx     = (const int*)  d_in[0];
    const int*   targets = (const int*)  d_in[1];
    const float* wte     = (const float*)d_in[2];
    const float* wpe     = (const float*)d_in[3];
    const float* ln1_w   = (const float*)d_in[4];
    const float* ln1_b   = (const float*)d_in[5];
    const float* attn_w  = (const float*)d_in[6];
    const float* attn_b  = (const float*)d_in[7];
    const float* aproj_w = (const float*)d_in[8];
    const float* aproj_b = (const float*)d_in[9];
    const float* ln2_w   = (const float*)d_in[10];
    const float* ln2_b   = (const float*)d_in[11];
    const float* fc_w    = (const float*)d_in[12];
    const float* fc_b    = (const float*)d_in[13];
    const float* mproj_w = (const float*)d_in[14];
    const float* mproj_b = (const float*)d_in[15];
    const float* lnf_w   = (const float*)d_in[16];
    const float* lnf_b   = (const float*)d_in[17];

    float *px, *pln, *pqkv, *patt, *py, *pfc, *pfb;
    bf16 *pah, *pal, *pwqh, *pwql, *pwah, *pwal, *pwfh, *pwfl, *pwmh, *pwml, *pteh, *ptel;
    cudaGetSymbolAddress((void**)&px,   g_x);
    cudaGetSymbolAddress((void**)&pln,  g_ln);
    cudaGetSymbolAddress((void**)&pqkv, g_qkv);
    cudaGetSymbolAddress((void**)&patt, g_att);
    cudaGetSymbolAddress((void**)&py,   g_y);
    cudaGetSymbolAddress((void**)&pfc,  g_fc);
    cudaGetSymbolAddress((void**)&pfb,  g_logits_fb);
    cudaGetSymbolAddress((void**)&pah,  g_ah);
    cudaGetSymbolAddress((void**)&pal,  g_al);
    cudaGetSymbolAddress((void**)&pwqh, g_wqkv_h);
    cudaGetSymbolAddress((void**)&pwql, g_wqkv_l);
    cudaGetSymbolAddress((void**)&pwah, g_wapr_h);
    cudaGetSymbolAddress((void**)&pwal, g_wapr_l);
    cudaGetSymbolAddress((void**)&pwfh, g_wfc_h);
    cudaGetSymbolAddress((void**)&pwfl, g_wfc_l);
    cudaGetSymbolAddress((void**)&pwmh, g_wmp_h);
    cudaGetSymbolAddress((void**)&pwml, g_wmp_l);
    cudaGetSymbolAddress((void**)&pteh, g_wte_h);
    cudaGetSymbolAddress((void**)&ptel, g_wte_l);

    cudaFuncSetAttribute(gemm_hmma, cudaFuncAttributeMaxDynamicSharedMemorySize, GSM_TOTAL);

    const long long BTV = (long long)BT * V_;
    float* logits = ((long long)out_size >= BTV) ? (float*)d_out : pfb;

    // weight conversions (transposed to [N,K] K-major, split hi/lo)
    dim3 tb(32, 8);
    transpose_split<<<dim3(C3 / 32, C_ / 32, L_), tb>>>(attn_w,  pwqh, pwql, C_, C3);
    transpose_split<<<dim3(C_ / 32, C_ / 32, L_), tb>>>(aproj_w, pwah, pwal, C_, C_);
    transpose_split<<<dim3(C4 / 32, C_ / 32, L_), tb>>>(fc_w,    pwfh, pwfl, C_, C4);
    transpose_split<<<dim3(C_ / 32, C4 / 32, L_), tb>>>(mproj_w, pwmh, pwml, C4, C_);
    convert_split<<<4096, 256>>>(wte, pteh, ptel, V_ * C_);

    embed_k<<<BT, 256>>>(idx, wte, wpe, px);

    for (int l = 0; l < L_; l++) {
        layernorm_k<<<BT, 256>>>(px, ln1_w + (size_t)l * C_, ln1_b + (size_t)l * C_, pln);
        convert_split<<<2048, 256>>>(pln, pah, pal, BT * C_);
        gemm_hmma<<<dim3(C3 / 128, BT / 128), 256, GSM_TOTAL>>>(
            pah, pal, pwqh + (size_t)l * C_ * C3, pwql + (size_t)l * C_ * C3,
            attn_b + (size_t)l * C3, nullptr, pqkv, BT, C3, C_, FUSE_NONE);

        attn_scores<<<dim3(T_ / 32, T_ / 32, B_ * H_), dim3(32, 32)>>>(pqkv, patt);
        softmax_rows<<<B_ * H_ * T_, 256>>>(patt);
        attn_av<<<dim3(T_ / 32, 1, B_ * H_), 256>>>(patt, pqkv, py);

        convert_split<<<2048, 256>>>(py, pah, pal, BT * C_);
        gemm_hmma<<<dim3(C_ / 128, BT / 128), 256, GSM_TOTAL>>>(
            pah, pal, pwah + (size_t)l * C_ * C_, pwal + (size_t)l * C_ * C_,
            aproj_b + (size_t)l * C_, px, px, BT, C_, C_, FUSE_RES);

        layernorm_k<<<BT, 256>>>(px, ln2_w + (size_t)l * C_, ln2_b + (size_t)l * C_, pln);
        convert_split<<<2048, 256>>>(pln, pah, pal, BT * C_);
        gemm_hmma<<<dim3(C4 / 128, BT / 128), 256, GSM_TOTAL>>>(
            pah, pal, pwfh + (size_t)l * C_ * C4, pwfl + (size_t)l * C_ * C4,
            fc_b + (size_t)l * C4, nullptr, pfc, BT, C4, C_, FUSE_GELU);

        convert_split<<<4096, 256>>>(pfc, pah, pal, BT * C4);
        gemm_hmma<<<dim3(C_ / 128, BT / 128), 256, GSM_TOTAL>>>(
            pah, pal, pwmh + (size_t)l * C4 * C_, pwml + (size_t)l * C4 * C_,
            mproj_b + (size_t)l * C_, px, px, BT, C_, C4, FUSE_RES);
    }

    layernorm_k<<<BT, 256>>>(px, lnf_w, lnf_b, pln);
    convert_split<<<2048, 256>>>(pln, pah, pal, BT * C_);

    int nbx = (V_ + 127) / 128;   // 393
    gemm_hmma<<<dim3(nbx, BT / 128), 256, GSM_TOTAL>>>(
        pah, pal, pteh, ptel, nullptr, nullptr, logits, BT, V_, C_, FUSE_NONE);

    zero_loss_k<<<1, 1>>>();
    loss_rows<<<BT, 256>>>(logits, targets);

    int loss_idx = -1;
    if ((long long)out_size == BTV + 1) loss_idx = (int)BTV;
    else if (out_size == 1)             loss_idx = 0;
    if (loss_idx >= 0) finalize_loss<<<1, 1>>>((float*)d_out, loss_idx);
}

// round 5
// speedup vs baseline: 2.7052x; 1.4224x over previous
#include <cuda_runtime.h>
#include <cuda_bf16.h>
#include <math.h>
#include <stdint.h>

#define B_  2
#define T_  1024
#define C_  768
#define L_  12
#define H_  12
#define V_  50257
#define D_  64
#define BT  (B_*T_)          // 2048
#define C3  (3*C_)           // 2304
#define C4  (4*C_)           // 3072

typedef __nv_bfloat16 bf16;

// ---------------- scratch (device globals) ----------------
__device__ float g_x  [BT*C_];
__device__ float g_logits_fb[(size_t)BT*V_];
__device__ float g_loss_sum;
__device__ int   g_valid_cnt;

// split-bf16 activations
__device__ bf16 g_lnh[BT*C_],  g_lnl[BT*C_];
__device__ bf16 g_qkvh[BT*C3], g_qkvl[BT*C3];
__device__ bf16 g_yh[BT*C_],   g_yl[BT*C_];
__device__ bf16 g_fch[BT*C4],  g_fcl[BT*C4];

// split-bf16 weights
__device__ bf16 g_wqkv_h[(size_t)L_*C_*C3], g_wqkv_l[(size_t)L_*C_*C3];
__device__ bf16 g_wapr_h[(size_t)L_*C_*C_], g_wapr_l[(size_t)L_*C_*C_];
__device__ bf16 g_wfc_h [(size_t)L_*C_*C4], g_wfc_l [(size_t)L_*C_*C4];
__device__ bf16 g_wmp_h [(size_t)L_*C4*C_], g_wmp_l [(size_t)L_*C4*C_];
__device__ bf16 g_wte_h [(size_t)V_*C_],    g_wte_l [(size_t)V_*C_];

// ---------------- ptx helpers ----------------
__device__ __forceinline__ uint32_t smem_u32(const void* p) {
    uint32_t a;
    asm("{ .reg .u64 t; cvta.to.shared.u64 t, %1; cvt.u32.u64 %0, t; }" : "=r"(a) : "l"(p));
    return a;
}
template<int N> __device__ __forceinline__ void cp_wait() {
    asm volatile("cp.async.wait_group %0;" :: "n"(N) : "memory");
}
__device__ __forceinline__ void cp_commit() {
    asm volatile("cp.async.commit_group;" ::: "memory");
}
__device__ __forceinline__ void cp16(uint32_t dst, const void* src, int sz) {
    asm volatile("cp.async.cg.shared.global [%0], [%1], 16, %2;"
                 :: "r"(dst), "l"(src), "r"(sz) : "memory");
}
__device__ __forceinline__ void ldsm4(uint32_t* r, uint32_t a) {
    asm volatile("ldmatrix.sync.aligned.m8n8.x4.shared.b16 {%0,%1,%2,%3}, [%4];"
                 : "=r"(r[0]), "=r"(r[1]), "=r"(r[2]), "=r"(r[3]) : "r"(a));
}
__device__ __forceinline__ void mma16816(float* d, const uint32_t* a, const uint32_t* b) {
    asm volatile("mma.sync.aligned.m16n8k16.row.col.f32.bf16.bf16.f32 "
                 "{%0,%1,%2,%3}, {%4,%5,%6,%7}, {%8,%9}, {%0,%1,%2,%3};"
                 : "+f"(d[0]), "+f"(d[1]), "+f"(d[2]), "+f"(d[3])
                 : "r"(a[0]), "r"(a[1]), "r"(a[2]), "r"(a[3]), "r"(b[0]), "r"(b[1]));
}
__device__ __forceinline__ uint32_t pack_bf2(float a, float b) {
    __nv_bfloat162 t = __floats2bfloat162_rn(a, b);
    return *(uint32_t*)&t;
}

__device__ __forceinline__ float gelu_f(float x) {
    const float k = 0.7978845608028654f;
    float x3 = x * x * x;
    return 0.5f * x * (1.0f + tanhf(k * (x + 0.044715f * x3)));
}

// ---------------- conversion kernels (weights only) ----------------
__global__ void convert_split(const float* __restrict__ in, bf16* __restrict__ hi,
                              bf16* __restrict__ lo, int n) {
    int i = blockIdx.x * blockDim.x + threadIdx.x;
    int stride = gridDim.x * blockDim.x;
    for (; i < n; i += stride) {
        float v = in[i];
        bf16 h = __float2bfloat16_rn(v);
        hi[i] = h;
        lo[i] = __float2bfloat16_rn(v - __bfloat162float(h));
    }
}

__global__ void transpose_split(const float* __restrict__ in, bf16* __restrict__ hi,
                                bf16* __restrict__ lo, int K, int N) {
    int l = blockIdx.z;
    in += (size_t)l * K * N;
    hi += (size_t)l * K * N;
    lo += (size_t)l * K * N;
    __shared__ float t[32][33];
    int n0 = blockIdx.x * 32, k0 = blockIdx.y * 32;
    #pragma unroll
    for (int i = 0; i < 4; i++) {
        int k = threadIdx.y + i * 8;
        t[k][threadIdx.x] = in[(size_t)(k0 + k) * N + n0 + threadIdx.x];
    }
    __syncthreads();
    #pragma unroll
    for (int i = 0; i < 4; i++) {
        int n = threadIdx.y + i * 8;
        float v = t[threadIdx.x][n];
        bf16 h = __float2bfloat16_rn(v);
        size_t o = (size_t)(n0 + n) * K + k0 + threadIdx.x;
        hi[o] = h;
        lo[o] = __float2bfloat16_rn(v - __bfloat162float(h));
    }
}

// ---------------- HMMA split-bf16 GEMM ----------------
#define FUSE_NONE 0
#define FUSE_RES  1
#define FUSE_GELU 2
#define GSTG 32768
#define GSM_TOTAL (2*GSTG)

__device__ __forceinline__ uint32_t swoff(int r, int c) {
    return (uint32_t)(r * 64 + ((c ^ ((r >> 1) & 3)) << 4));
}

// If OutH != null: write split bf16 (requires N%128==0). Else f32 to Cm.
__global__ __launch_bounds__(256)
void gemm_hmma(const bf16* __restrict__ Ah, const bf16* __restrict__ Al,
               const bf16* __restrict__ Bh, const bf16* __restrict__ Bl,
               const float* __restrict__ bias, const float* __restrict__ res,
               float* __restrict__ Cm, bf16* __restrict__ OutH, bf16* __restrict__ OutL,
               int M, int N, int K, int fuse) {
    extern __shared__ char smem[];
    uint32_t sb = smem_u32(smem);
    int tid = threadIdx.x, lane = tid & 31, w = tid >> 5;
    int wm0 = (w & 3) * 32, wn0 = (w >> 2) * 64;
    int m0 = blockIdx.y * 128, n0 = blockIdx.x * 128;

    float acc[2][8][4];
    #pragma unroll
    for (int i = 0; i < 2; i++)
        #pragma unroll
        for (int j = 0; j < 8; j++)
            #pragma unroll
            for (int k = 0; k < 4; k++) acc[i][j][k] = 0.f;

    int cr = tid >> 2, cb = tid & 3;
    int nch = K >> 5;
    int rowoff = (lane & 7) + ((lane >> 3) & 1) * 8;
    int cbh = lane >> 4;

    {
        uint32_t base = sb;
        #pragma unroll
        for (int i = 0; i < 2; i++) {
            int r = cr + i * 64;
            uint32_t d = swoff(r, cb);
            size_t ao = (size_t)(m0 + r) * K + cb * 8;
            cp16(base + d, Ah + ao, 16);
            cp16(base + 8192 + d, Al + ao, 16);
            int nr = n0 + r;
            int nc = nr < N ? nr : (N - 1);
            int sz = nr < N ? 16 : 0;
            size_t bo = (size_t)nc * K + cb * 8;
            cp16(base + 16384 + d, Bh + bo, sz);
            cp16(base + 24576 + d, Bl + bo, sz);
        }
        cp_commit();
    }

    for (int ch = 0; ch < nch; ch++) {
        if (ch + 1 < nch) {
            int k0 = (ch + 1) * 32;
            uint32_t base = sb + ((ch + 1) & 1) * GSTG;
            #pragma unroll
            for (int i = 0; i < 2; i++) {
                int r = cr + i * 64;
                uint32_t d = swoff(r, cb);
                size_t ao = (size_t)(m0 + r) * K + k0 + cb * 8;
                cp16(base + d, Ah + ao, 16);
                cp16(base + 8192 + d, Al + ao, 16);
                int nr = n0 + r;
                int nc = nr < N ? nr : (N - 1);
                int sz = nr < N ? 16 : 0;
                size_t bo = (size_t)nc * K + k0 + cb * 8;
                cp16(base + 16384 + d, Bh + bo, sz);
                cp16(base + 24576 + d, Bl + bo, sz);
            }
            cp_commit();
            cp_wait<1>();
        } else {
            cp_wait<0>();
        }
        __syncthreads();

        uint32_t aB = sb + (ch & 1) * GSTG;
        uint32_t bB = aB + 16384;
        #pragma unroll
        for (int ks = 0; ks < 2; ks++) {
            uint32_t ah[2][4], al[2][4];
            #pragma unroll
            for (int mi = 0; mi < 2; mi++) {
                int row = wm0 + mi * 16 + rowoff;
                uint32_t ad = aB + (uint32_t)(row * 64) +
                              (uint32_t)((((2 * ks + cbh) ^ ((row >> 1) & 3))) << 4);
                ldsm4(ah[mi], ad);
                ldsm4(al[mi], ad + 8192);
            }
            uint32_t bh[8][2], bl[8][2];
            #pragma unroll
            for (int nj = 0; nj < 4; nj++) {
                int row = wn0 + nj * 16 + rowoff;
                uint32_t bd = bB + (uint32_t)(row * 64) +
                              (uint32_t)((((2 * ks + cbh) ^ ((row >> 1) & 3))) << 4);
                uint32_t q[4];
                ldsm4(q, bd);
                bh[2 * nj][0] = q[0]; bh[2 * nj][1] = q[2];
                bh[2 * nj + 1][0] = q[1]; bh[2 * nj + 1][1] = q[3];
                ldsm4(q, bd + 8192);
                bl[2 * nj][0] = q[0]; bl[2 * nj][1] = q[2];
                bl[2 * nj + 1][0] = q[1]; bl[2 * nj + 1][1] = q[3];
            }
            #pragma unroll
            for (int mi = 0; mi < 2; mi++)
                #pragma unroll
                for (int ni = 0; ni < 8; ni++) {
                    mma16816(acc[mi][ni], ah[mi], bh[ni]);
                    mma16816(acc[mi][ni], ah[mi], bl[ni]);
                    mma16816(acc[mi][ni], al[mi], bh[ni]);
                }
        }
        __syncthreads();
    }

    int r0 = lane >> 2, c0 = (lane & 3) * 2;
    bool vec_ok = (n0 + 128 <= N) && ((N & 1) == 0);
    #pragma unroll
    for (int mi = 0; mi < 2; mi++) {
        #pragma unroll
        for (int ni = 0; ni < 8; ni++) {
            int gr = m0 + wm0 + mi * 16 + r0;
            int gc = n0 + wn0 + ni * 8 + c0;
            float v0 = acc[mi][ni][0], v1 = acc[mi][ni][1];
            float v2 = acc[mi][ni][2], v3 = acc[mi][ni][3];
            if (vec_ok) {
                if (bias) { float b0 = bias[gc], b1 = bias[gc + 1]; v0 += b0; v1 += b1; v2 += b0; v3 += b1; }
                if (fuse == FUSE_RES) {
                    const float* r1p = res + (size_t)gr * N + gc;
                    const float* r2p = res + (size_t)(gr + 8) * N + gc;
                    v0 += r1p[0]; v1 += r1p[1]; v2 += r2p[0]; v3 += r2p[1];
                } else if (fuse == FUSE_GELU) {
                    v0 = gelu_f(v0); v1 = gelu_f(v1); v2 = gelu_f(v2); v3 = gelu_f(v3);
                }
                if (OutH) {
                    bf16 h0 = __float2bfloat16_rn(v0), h1 = __float2bfloat16_rn(v1);
                    bf16 h2 = __float2bfloat16_rn(v2), h3 = __float2bfloat16_rn(v3);
                    *(uint32_t*)(OutH + (size_t)gr * N + gc)       = pack_bf2(v0, v1) * 0 + (*(uint16_t*)&h0 | ((uint32_t)*(uint16_t*)&h1 << 16));
                    *(uint32_t*)(OutH + (size_t)(gr + 8) * N + gc) = (*(uint16_t*)&h2 | ((uint32_t)*(uint16_t*)&h3 << 16));
                    float l0 = v0 - __bfloat162float(h0), l1 = v1 - __bfloat162float(h1);
                    float l2 = v2 - __bfloat162float(h2), l3 = v3 - __bfloat162float(h3);
                    *(uint32_t*)(OutL + (size_t)gr * N + gc)       = pack_bf2(l0, l1);
                    *(uint32_t*)(OutL + (size_t)(gr + 8) * N + gc) = pack_bf2(l2, l3);
                } else {
                    *(float2*)(Cm + (size_t)gr * N + gc)       = make_float2(v0, v1);
                    *(float2*)(Cm + (size_t)(gr + 8) * N + gc) = make_float2(v2, v3);
                }
            } else {
                if (gc < N) {
                    float b0 = bias ? bias[gc] : 0.f;
                    float a0 = v0 + b0, a2 = v2 + b0;
                    if (fuse == FUSE_RES) { a0 += res[(size_t)gr * N + gc]; a2 += res[(size_t)(gr + 8) * N + gc]; }
                    else if (fuse == FUSE_GELU) { a0 = gelu_f(a0); a2 = gelu_f(a2); }
                    Cm[(size_t)gr * N + gc] = a0;
                    Cm[(size_t)(gr + 8) * N + gc] = a2;
                }
                if (gc + 1 < N) {
                    float b1 = bias ? bias[gc + 1] : 0.f;
                    float a1 = v1 + b1, a3 = v3 + b1;
                    if (fuse == FUSE_RES) { a1 += res[(size_t)gr * N + gc + 1]; a3 += res[(size_t)(gr + 8) * N + gc + 1]; }
                    else if (fuse == FUSE_GELU) { a1 = gelu_f(a1); a3 = gelu_f(a3); }
                    Cm[(size_t)gr * N + gc + 1] = a1;
                    Cm[(size_t)(gr + 8) * N + gc + 1] = a3;
                }
            }
        }
    }
}

// ---------------- flash attention (split-bf16 HMMA, online softmax) ----------
// grid (T/64, B*H), 128 threads (4 warps x 16 q-rows). K tile 64x64, V^T 64x64.
#define FPAD 72
__global__ __launch_bounds__(128)
void flash_attn(const bf16* __restrict__ qkvh, const bf16* __restrict__ qkvl,
                bf16* __restrict__ yh, bf16* __restrict__ yl) {
    __shared__ bf16 kh[64][FPAD], kl[64][FPAD];
    __shared__ bf16 vth[64][FPAD], vtl[64][FPAD];
    int qt = blockIdx.x, bh = blockIdx.y;
    int b = bh / H_, h = bh % H_;
    int tid = threadIdx.x, w = tid >> 5, lane = tid & 31;
    int g = lane >> 2, tg = lane & 3;
    int t0 = qt * 64;
    int row = t0 + w * 16 + g;                    // q row for c0/c1 frags
    size_t grA = (size_t)(b * T_ + row) * C3 + h * D_;
    size_t grB = grA + (size_t)8 * C3;

    // load Q A-fragments (resident): [kfrag][a0..a3], hi and lo
    uint32_t qah[4][4], qal[4][4];
    #pragma unroll
    for (int kk = 0; kk < 4; kk++) {
        int k = kk * 16 + tg * 2;
        qah[kk][0] = *(const uint32_t*)(qkvh + grA + k);
        qah[kk][1] = *(const uint32_t*)(qkvh + grB + k);
        qah[kk][2] = *(const uint32_t*)(qkvh + grA + k + 8);
        qah[kk][3] = *(const uint32_t*)(qkvh + grB + k + 8);
        qal[kk][0] = *(const uint32_t*)(qkvl + grA + k);
        qal[kk][1] = *(const uint32_t*)(qkvl + grB + k);
        qal[kk][2] = *(const uint32_t*)(qkvl + grA + k + 8);
        qal[kk][3] = *(const uint32_t*)(qkvl + grB + k + 8);
    }

    float O[8][4];
    #pragma unroll
    for (int i = 0; i < 8; i++)
        #pragma unroll
        for (int j = 0; j < 4; j++) O[i][j] = 0.f;
    float m0 = -1e30f, m1 = -1e30f, l0 = 0.f, l1 = 0.f;

    for (int st = 0; st <= qt; st++) {
        int s0 = st * 64;
        // cooperative load K [s][d] and V^T [d][s]
        for (int e = tid; e < 64 * 32; e += 128) {
            int r = e >> 5, j = (e & 31) * 2;
            size_t gk = (size_t)(b * T_ + s0 + r) * C3 + C_ + h * D_ + j;
            *(uint32_t*)&kh[r][j] = *(const uint32_t*)(qkvh + gk);
            *(uint32_t*)&kl[r][j] = *(const uint32_t*)(qkvl + gk);
            size_t gv = gk + C_;
            uint32_t wh = *(const uint32_t*)(qkvh + gv);
            uint32_t wl = *(const uint32_t*)(qkvl + gv);
            vth[j][r]     = *(bf16*)&wh;
            vth[j + 1][r] = *((bf16*)&wh + 1);
            vtl[j][r]     = *(bf16*)&wl;
            vtl[j + 1][r] = *((bf16*)&wl + 1);
        }
        __syncthreads();

        // S = Q @ K^T (split)
        float S[8][4];
        #pragma unroll
        for (int nf = 0; nf < 8; nf++) {
            S[nf][0] = S[nf][1] = S[nf][2] = S[nf][3] = 0.f;
            int n = nf * 8 + g;
            #pragma unroll
            for (int kk = 0; kk < 4; kk++) {
                int k = kk * 16 + tg * 2;
                uint32_t bfr[2], bfl[2];
                bfr[0] = *(const uint32_t*)&kh[n][k];
                bfr[1] = *(const uint32_t*)&kh[n][k + 8];
                bfl[0] = *(const uint32_t*)&kl[n][k];
                bfl[1] = *(const uint32_t*)&kl[n][k + 8];
                mma16816(S[nf], qah[kk], bfr);
                mma16816(S[nf], qah[kk], bfl);
                mma16816(S[nf], qal[kk], bfr);
            }
        }

        // scale + causal mask
        bool diag = (st == qt);
        #pragma unroll
        for (int nf = 0; nf < 8; nf++) {
            int cbase = s0 + nf * 8 + tg * 2;
            #pragma unroll
            for (int j = 0; j < 4; j++) {
                S[nf][j] *= 0.125f;
                if (diag) {
                    int cc = cbase + (j & 1);
                    int rr = row + (j >> 1) * 8;
                    if (cc > rr) S[nf][j] = -1e30f;
                }
            }
        }

        // online softmax
        float rm0 = -1e30f, rm1 = -1e30f;
        #pragma unroll
        for (int nf = 0; nf < 8; nf++) {
            rm0 = fmaxf(rm0, fmaxf(S[nf][0], S[nf][1]));
            rm1 = fmaxf(rm1, fmaxf(S[nf][2], S[nf][3]));
        }
        rm0 = fmaxf(rm0, __shfl_xor_sync(0xffffffffu, rm0, 1));
        rm0 = fmaxf(rm0, __shfl_xor_sync(0xffffffffu, rm0, 2));
        rm1 = fmaxf(rm1, __shfl_xor_sync(0xffffffffu, rm1, 1));
        rm1 = fmaxf(rm1, __shfl_xor_sync(0xffffffffu, rm1, 2));
        float mn0 = fmaxf(m0, rm0), mn1 = fmaxf(m1, rm1);
        float cr0 = __expf(m0 - mn0), cr1 = __expf(m1 - mn1);
        m0 = mn0; m1 = mn1;

        uint32_t ph[8][2], pl[8][2];
        float ls0 = 0.f, ls1 = 0.f;
        #pragma unroll
        for (int nf = 0; nf < 8; nf++) {
            float p0 = __expf(S[nf][0] - m0), p1 = __expf(S[nf][1] - m0);
            float p2 = __expf(S[nf][2] - m1), p3 = __expf(S[nf][3] - m1);
            ls0 += p0 + p1; ls1 += p2 + p3;
            bf16 h0 = __float2bfloat16_rn(p0), h1 = __float2bfloat16_rn(p1);
            bf16 h2 = __float2bfloat16_rn(p2), h3 = __float2bfloat16_rn(p3);
            ph[nf][0] = (*(uint16_t*)&h0) | ((uint32_t)(*(uint16_t*)&h1) << 16);
            ph[nf][1] = (*(uint16_t*)&h2) | ((uint32_t)(*(uint16_t*)&h3) << 16);
            pl[nf][0] = pack_bf2(p0 - __bfloat162float(h0), p1 - __bfloat162float(h1));
            pl[nf][1] = pack_bf2(p2 - __bfloat162float(h2), p3 - __bfloat162float(h3));
        }
        l0 = l0 * cr0 + ls0;
        l1 = l1 * cr1 + ls1;
        #pragma unroll
        for (int nf = 0; nf < 8; nf++) {
            O[nf][0] *= cr0; O[nf][1] *= cr0;
            O[nf][2] *= cr1; O[nf][3] *= cr1;
        }

        // O += P @ V (split)
        #pragma unroll
        for (int kk = 0; kk < 4; kk++) {
            uint32_t pah[4] = { ph[2*kk][0], ph[2*kk][1], ph[2*kk+1][0], ph[2*kk+1][1] };
            uint32_t pal[4] = { pl[2*kk][0], pl[2*kk][1], pl[2*kk+1][0], pl[2*kk+1][1] };
            #pragma unroll
            for (int nf = 0; nf < 8; nf++) {
                int n = nf * 8 + g;
                int k = kk * 16 + tg * 2;
                uint32_t vbh[2], vbl[2];
                vbh[0] = *(const uint32_t*)&vth[n][k];
                vbh[1] = *(const uint32_t*)&vth[n][k + 8];
                vbl[0] = *(const uint32_t*)&vtl[n][k];
                vbl[1] = *(const uint32_t*)&vtl[n][k + 8];
                mma16816(O[nf], pah, vbh);
                mma16816(O[nf], pah, vbl);
                mma16816(O[nf], pal, vbh);
            }
        }
        __syncthreads();
    }

    // final normalize + write split y
    l0 += __shfl_xor_sync(0xffffffffu, l0, 1);
    l0 += __shfl_xor_sync(0xffffffffu, l0, 2);
    l1 += __shfl_xor_sync(0xffffffffu, l1, 1);
    l1 += __shfl_xor_sync(0xffffffffu, l1, 2);
    float inv0 = 1.0f / l0, inv1 = 1.0f / l1;
    size_t yo0 = (size_t)(b * T_ + row) * C_ + h * D_;
    size_t yo1 = yo0 + (size_t)8 * C_;
    #pragma unroll
    for (int nf = 0; nf < 8; nf++) {
        int d = nf * 8 + tg * 2;
        float v0 = O[nf][0] * inv0, v1 = O[nf][1] * inv0;
        float v2 = O[nf][2] * inv1, v3 = O[nf][3] * inv1;
        bf16 h0 = __float2bfloat16_rn(v0), h1 = __float2bfloat16_rn(v1);
        bf16 h2 = __float2bfloat16_rn(v2), h3 = __float2bfloat16_rn(v3);
        *(uint32_t*)(yh + yo0 + d) = (*(uint16_t*)&h0) | ((uint32_t)(*(uint16_t*)&h1) << 16);
        *(uint32_t*)(yh + yo1 + d) = (*(uint16_t*)&h2) | ((uint32_t)(*(uint16_t*)&h3) << 16);
        *(uint32_t*)(yl + yo0 + d) = pack_bf2(v0 - __bfloat162float(h0), v1 - __bfloat162float(h1));
        *(uint32_t*)(yl + yo1 + d) = pack_bf2(v2 - __bfloat162float(h2), v3 - __bfloat162float(h3));
    }
}

// ---------------- embedding ----------------
__global__ void embed_k(const int* __restrict__ idx, const float* __restrict__ wte,
                        const float* __restrict__ wpe, float* __restrict__ x) {
    int row = blockIdx.x;
    int t = row % T_;
    int tok = idx[row];
    const float* pe = wpe + (size_t)t * C_;
    const float* pw = wte + (size_t)tok * C_;
    float* po = x + (size_t)row * C_;
    for (int i = threadIdx.x; i < C_; i += blockDim.x) po[i] = pw[i] + pe[i];
}

// ---------------- layernorm -> split bf16 ----------------
__global__ void layernorm_split(const float* __restrict__ x, const float* __restrict__ w,
                                const float* __restrict__ b, bf16* __restrict__ oh,
                                bf16* __restrict__ ol) {
    int row = blockIdx.x;
    const float* px = x + (size_t)row * C_;
    __shared__ float red[256];
    int tid = threadIdx.x;

    float s = 0.f;
    for (int i = tid; i < C_; i += 256) s += px[i];
    red[tid] = s; __syncthreads();
    for (int off = 128; off > 0; off >>= 1) { if (tid < off) red[tid] += red[tid + off]; __syncthreads(); }
    float mean = red[0] * (1.0f / C_);
    __syncthreads();

    float v = 0.f;
    for (int i = tid; i < C_; i += 256) { float d = px[i] - mean; v += d * d; }
    red[tid] = v; __syncthreads();
    for (int off = 128; off > 0; off >>= 1) { if (tid < off) red[tid] += red[tid + off]; __syncthreads(); }
    float rstd = rsqrtf(red[0] * (1.0f / C_) + 1e-5f);

    for (int i = tid; i < C_; i += 256) {
        float o = (px[i] - mean) * rstd * w[i] + b[i];
        bf16 h = __float2bfloat16_rn(o);
        oh[(size_t)row * C_ + i] = h;
        ol[(size_t)row * C_ + i] = __float2bfloat16_rn(o - __bfloat162float(h));
    }
}

// ---------------- loss ----------------
__global__ void zero_loss_k() { g_loss_sum = 0.f; g_valid_cnt = 0; }

__global__ void loss_rows(const float* __restrict__ logits, const int* __restrict__ targets) {
    int row = blockIdx.x;
    const float* p = logits + (size_t)row * V_;
    __shared__ float red[256];
    int tid = threadIdx.x;

    float m = -INFINITY;
    for (int i = tid; i < V_; i += 256) m = fmaxf(m, p[i]);
    red[tid] = m; __syncthreads();
    for (int off = 128; off > 0; off >>= 1) { if (tid < off) red[tid] = fmaxf(red[tid], red[tid + off]); __syncthreads(); }
    m = red[0]; __syncthreads();

    float sum = 0.f;
    for (int i = tid; i < V_; i += 256) sum += expf(p[i] - m);
    red[tid] = sum; __syncthreads();
    for (int off = 128; off > 0; off >>= 1) { if (tid < off) red[tid] += red[tid + off]; __syncthreads(); }
    sum = red[0];

    if (tid == 0) {
        int t = targets[row];
        if (t != -1) {
            float nll = -(p[t] - m - logf(sum));
            atomicAdd(&g_loss_sum, nll);
            atomicAdd(&g_valid_cnt, 1);
        }
    }
}

__global__ void finalize_loss(float* out, int loss_idx) {
    int v = g_valid_cnt; if (v < 1) v = 1;
    out[loss_idx] = g_loss_sum / (float)v;
}

// ---------------- host launcher ----------------
extern "C" void kernel_launch(void* const* d_in, const int* in_sizes, int n_in,
                              void* d_out, int out_size) {
    const int*   idx     = (const int*)  d_in[0];
    const int*   targets = (const int*)  d_in[1];
    const float* wte     = (const float*)d_in[2];
    const float* wpe     = (const float*)d_in[3];
    const float* ln1_w   = (const float*)d_in[4];
    const float* ln1_b   = (const float*)d_in[5];
    const float* attn_w  = (const float*)d_in[6];
    const float* attn_b  = (const float*)d_in[7];
    const float* aproj_w = (const float*)d_in[8];
    const float* aproj_b = (const float*)d_in[9];
    const float* ln2_w   = (const float*)d_in[10];
    const float* ln2_b   = (const float*)d_in[11];
    const float* fc_w    = (const float*)d_in[12];
    const float* fc_b    = (const float*)d_in[13];
    const float* mproj_w = (const float*)d_in[14];
    const float* mproj_b = (const float*)d_in[15];
    const float* lnf_w   = (const float*)d_in[16];
    const float* lnf_b   = (const float*)d_in[17];

    float *px, *pfb;
    bf16 *plnh, *plnl, *pqkvh, *pqkvl, *pyh, *pyl, *pfch, *pfcl;
    bf16 *pwqh, *pwql, *pwah, *pwal, *pwfh, *pwfl, *pwmh, *pwml, *pteh, *ptel;
    cudaGetSymbolAddress((void**)&px,    g_x);
    cudaGetSymbolAddress((void**)&pfb,   g_logits_fb);
    cudaGetSymbolAddress((void**)&plnh,  g_lnh);
    cudaGetSymbolAddress((void**)&plnl,  g_lnl);
    cudaGetSymbolAddress((void**)&pqkvh, g_qkvh);
    cudaGetSymbolAddress((void**)&pqkvl, g_qkvl);
    cudaGetSymbolAddress((void**)&pyh,   g_yh);
    cudaGetSymbolAddress((void**)&pyl,   g_yl);
    cudaGetSymbolAddress((void**)&pfch,  g_fch);
    cudaGetSymbolAddress((void**)&pfcl,  g_fcl);
    cudaGetSymbolAddress((void**)&pwqh,  g_wqkv_h);
    cudaGetSymbolAddress((void**)&pwql,  g_wqkv_l);
    cudaGetSymbolAddress((void**)&pwah,  g_wapr_h);
    cudaGetSymbolAddress((void**)&pwal,  g_wapr_l);
    cudaGetSymbolAddress((void**)&pwfh,  g_wfc_h);
    cudaGetSymbolAddress((void**)&pwfl,  g_wfc_l);
    cudaGetSymbolAddress((void**)&pwmh,  g_wmp_h);
    cudaGetSymbolAddress((void**)&pwml,  g_wmp_l);
    cudaGetSymbolAddress((void**)&pteh,  g_wte_h);
    cudaGetSymbolAddress((void**)&ptel,  g_wte_l);

    cudaFuncSetAttribute(gemm_hmma, cudaFuncAttributeMaxDynamicSharedMemorySize, GSM_TOTAL);

    const long long BTV = (long long)BT * V_;
    float* logits = ((long long)out_size >= BTV) ? (float*)d_out : pfb;

    dim3 tb(32, 8);
    transpose_split<<<dim3(C3 / 32, C_ / 32, L_), tb>>>(attn_w,  pwqh, pwql, C_, C3);
    transpose_split<<<dim3(C_ / 32, C_ / 32, L_), tb>>>(aproj_w, pwah, pwal, C_, C_);
    transpose_split<<<dim3(C4 / 32, C_ / 32, L_), tb>>>(fc_w,    pwfh, pwfl, C_, C4);
    transpose_split<<<dim3(C_ / 32, C4 / 32, L_), tb>>>(mproj_w, pwmh, pwml, C4, C_);
    convert_split<<<4096, 256>>>(wte, pteh, ptel, V_ * C_);

    embed_k<<<BT, 256>>>(idx, wte, wpe, px);

    for (int l = 0; l < L_; l++) {
        layernorm_split<<<BT, 256>>>(px, ln1_w + (size_t)l * C_, ln1_b + (size_t)l * C_, plnh, plnl);
        gemm_hmma<<<dim3(C3 / 128, BT / 128), 256, GSM_TOTAL>>>(
            plnh, plnl, pwqh + (size_t)l * C_ * C3, pwql + (size_t)l * C_ * C3,
            attn_b + (size_t)l * C3, nullptr, nullptr, pqkvh, pqkvl, BT, C3, C_, FUSE_NONE);

        flash_attn<<<dim3(T_ / 64, B_ * H_), 128>>>(pqkvh, pqkvl, pyh, pyl);

        gemm_hmma<<<dim3(C_ / 128, BT / 128), 256, GSM_TOTAL>>>(
            pyh, pyl, pwah + (size_t)l * C_ * C_, pwal + (size_t)l * C_ * C_,
            aproj_b + (size_t)l * C_, px, px, nullptr, nullptr, BT, C_, C_, FUSE_RES);

        layernorm_split<<<BT, 256>>>(px, ln2_w + (size_t)l * C_, ln2_b + (size_t)l * C_, plnh, plnl);
        gemm_hmma<<<dim3(C4 / 128, BT / 128), 256, GSM_TOTAL>>>(
            plnh, plnl, pwfh + (size_t)l * C_ * C4, pwfl + (size_t)l * C_ * C4,
            fc_b + (size_t)l * C4, nullptr, nullptr, pfch, pfcl, BT, C4, C_, FUSE_GELU);

        gemm_hmma<<<dim3(C_ / 128, BT / 128), 256, GSM_TOTAL>>>(
            pfch, pfcl, pwmh + (size_t)l * C4 * C_, pwml + (size_t)l * C4 * C_,
            mproj_b + (size_t)l * C_, px, px, nullptr, nullptr, BT, C_, C4, FUSE_RES);
    }

    layernorm_split<<<BT, 256>>>(px, lnf_w, lnf_b, plnh, plnl);

    int nbx = (V_ + 127) / 128;
    gemm_hmma<<<dim3(nbx, BT / 128), 256, GSM_TOTAL>>>(
        plnh, plnl, pteh, ptel, nullptr, nullptr, logits, nullptr, nullptr, BT, V_, C_, FUSE_NONE);

    zero_loss_k<<<1, 1>>>();
    loss_rows<<<BT, 256>>>(logits, targets);

    int loss_idx = -1;
    if ((long long)out_size == BTV + 1) loss_idx = (int)BTV;
    else if (out_size == 1)             loss_idx = 0;
    if (loss_idx >= 0) finalize_loss<<<1, 1>>>((float*)d_out, loss_idx);
}